// round 5
// baseline (speedup 1.0000x reference)
#include <cuda_runtime.h>
#include <math.h>

#define H     2048
#define T     4096
#define G3    (3 * H)
#define K_IN  2048

// ---------------- device scratch / barrier state ----------------
__device__ float    g_ig[(size_t)T * G3];   // igates [T][3H]  (~100.7 MB)
__device__ unsigned g_bar_count;            // zero-init; returns to 0 after each barrier
__device__ unsigned g_bar_gen;              // monotonically increasing generation

// =================================================================
// Kernel 1: igates = xs @ Wi^T + bi    (fp32 SMEM-tiled GEMM)
// =================================================================
#define BM 128
#define BN 128
#define BK 16

__global__ __launch_bounds__(256, 2)
void igates_gemm(const float* __restrict__ A,
                 const float* __restrict__ B,
                 const float* __restrict__ bi)
{
    __shared__ float As[BK][BM + 4];
    __shared__ float Bs[BK][BN + 4];

    const int tid = threadIdx.x;
    const int m0  = blockIdx.y * BM;
    const int n0  = blockIdx.x * BN;
    const int tx  = tid & 15;
    const int ty  = tid >> 4;

    float acc[8][8];
#pragma unroll
    for (int i = 0; i < 8; i++)
#pragma unroll
        for (int j = 0; j < 8; j++) acc[i][j] = 0.f;

    for (int k0 = 0; k0 < K_IN; k0 += BK) {
#pragma unroll
        for (int p = 0; p < 2; p++) {
            int f   = tid + p * 256;
            int row = f >> 2;
            int c4  = (f & 3) * 4;
            float4 va = *reinterpret_cast<const float4*>(
                &A[(size_t)(m0 + row) * K_IN + k0 + c4]);
            As[c4 + 0][row] = va.x; As[c4 + 1][row] = va.y;
            As[c4 + 2][row] = va.z; As[c4 + 3][row] = va.w;
            float4 vb = *reinterpret_cast<const float4*>(
                &B[(size_t)(n0 + row) * K_IN + k0 + c4]);
            Bs[c4 + 0][row] = vb.x; Bs[c4 + 1][row] = vb.y;
            Bs[c4 + 2][row] = vb.z; Bs[c4 + 3][row] = vb.w;
        }
        __syncthreads();

#pragma unroll
        for (int kk = 0; kk < BK; kk++) {
            float a[8], b[8];
            *reinterpret_cast<float4*>(&a[0]) = *reinterpret_cast<float4*>(&As[kk][ty * 8]);
            *reinterpret_cast<float4*>(&a[4]) = *reinterpret_cast<float4*>(&As[kk][ty * 8 + 4]);
            *reinterpret_cast<float4*>(&b[0]) = *reinterpret_cast<float4*>(&Bs[kk][tx * 8]);
            *reinterpret_cast<float4*>(&b[4]) = *reinterpret_cast<float4*>(&Bs[kk][tx * 8 + 4]);
#pragma unroll
            for (int i = 0; i < 8; i++)
#pragma unroll
                for (int j = 0; j < 8; j++)
                    acc[i][j] = fmaf(a[i], b[j], acc[i][j]);
        }
        __syncthreads();
    }

#pragma unroll
    for (int i = 0; i < 8; i++) {
        int m = m0 + ty * 8 + i;
#pragma unroll
        for (int j = 0; j < 8; j += 4) {
            int n = n0 + tx * 8 + j;
            float4 v;
            v.x = acc[i][j + 0] + bi[n + 0];
            v.y = acc[i][j + 1] + bi[n + 1];
            v.z = acc[i][j + 2] + bi[n + 2];
            v.w = acc[i][j + 3] + bi[n + 3];
            *reinterpret_cast<float4*>(&g_ig[(size_t)m * G3 + n]) = v;
        }
    }
}

// =================================================================
// Kernel 2: persistent GRU scan, fully weight-resident (regs+SMEM)
//   148 CTAs x 512 threads (16 warps), 1 CTA/SM.
//   Each CTA owns nj<=14 hidden units -> 3*nj <= 42 weight rows.
//   Row slot rr = s*16 + warp, s=0..2.
//     slot 0 (rows 0..15):   weights in REGISTERS (64 floats/lane/row)
//     slots 1,2 (rows 16..41): weights in SMEM (loaded once)
//   igate loads for step t+1 are issued inside the barrier window.
// =================================================================
#define NSR_MAX 26
#define SCAN_SMEM ((NSR_MAX * H + H + 64) * 4)   // 221,440 bytes

__global__ __launch_bounds__(512, 1)
void gru_scan(const float* __restrict__ Wh,
              const float* __restrict__ init_state,
              const float* __restrict__ bn,
              float* __restrict__ out)
{
    extern __shared__ float smem[];
    const int NB   = gridDim.x;
    const int cta  = blockIdx.x;
    const int tid  = threadIdx.x;
    const int lane = tid & 31;
    const int warp = tid >> 5;          // 0..15

    const int chunk = (H + NB - 1) / NB;
    const int j0    = cta * chunk;
    int nj = H - j0;
    if (nj > chunk) nj = chunk;
    if (nj < 0) nj = 0;
    const int nrows = 3 * nj;

    float* sw    = smem;                 // NSR_MAX rows x 2048 (rows 16..41)
    float* sh    = smem + NSR_MAX * H;   // staged h (2048)
    float* sdots = sh + H;               // 48 dot results
    float4* sh4  = reinterpret_cast<float4*>(sh);

    // ---- preload SMEM-resident weight rows (rr = 16..nrows-1), once ----
    const int nsr = (nrows > 16) ? (nrows - 16) : 0;   // <= 26
    for (int idx = tid; idx < nsr * (H / 4); idx += 512) {
        int r  = idx >> 9;              // /512
        int c  = idx & 511;
        int rr = 16 + r;
        int g  = rr / nj;               // nj>0 whenever nsr>0
        int jj = rr - g * nj;
        reinterpret_cast<float4*>(sw)[r * (H / 4) + c] =
            reinterpret_cast<const float4*>(Wh + (size_t)(g * H + j0 + jj) * H)[c];
    }

    // ---- per-warp row slots ----
    const int rr0 = warp, rr1 = warp + 16, rr2 = warp + 32;
    const bool v0 = rr0 < nrows, v1 = rr1 < nrows, v2 = rr2 < nrows;

    // ---- register-resident weights for slot 0 ----
    float4 wreg[16];
    {
        int g  = v0 ? (rr0 / nj) : 0;
        int jj = v0 ? (rr0 - g * nj) : 0;
        const float* row = Wh + (size_t)(g * H + j0 + jj) * H;
#pragma unroll
        for (int i = 0; i < 16; i++)
            wreg[i] = reinterpret_cast<const float4*>(row)[lane + 32 * i];
    }

    // SMEM weight pointers for slots 1,2 (dummy -> sw base when invalid)
    const float4* p1 = reinterpret_cast<const float4*>(v1 ? (sw + (rr1 - 16) * H) : sw);
    const float4* p2 = reinterpret_cast<const float4*>(v2 ? (sw + (rr2 - 16) * H) : sw);

    unsigned seen = *reinterpret_cast<volatile unsigned*>(&g_bar_gen);

    const bool doPoint = (tid < nj);
    const int  myj     = j0 + (doPoint ? tid : 0);
    const float mybn   = doPoint ? bn[myj] : 0.f;

    // prefetch igates for t = 0
    float gr = 0.f, gz = 0.f, gnv = 0.f;
    if (doPoint) {
        gr  = g_ig[myj];
        gz  = g_ig[H + myj];
        gnv = g_ig[2 * H + myj];
    }

    __syncthreads();   // SMEM weights ready

#pragma unroll 1
    for (int t = 0; t < T; t++) {
        // ---- stage h_{t-1} into SMEM (8 KB from L2) ----
        const float* hsrc = (t == 0) ? init_state : (out + (size_t)(t - 1) * H);
        sh4[tid] = reinterpret_cast<const float4*>(hsrc)[tid];
        __syncthreads();

        // ---- three dot products per warp ----
        float a0 = 0.f, a1 = 0.f, a2 = 0.f;
#pragma unroll
        for (int i = 0; i < 16; i++) {
            const int k = lane + 32 * i;
            const float4 hv = sh4[k];
            a0 = fmaf(wreg[i].x, hv.x, a0); a0 = fmaf(wreg[i].y, hv.y, a0);
            a0 = fmaf(wreg[i].z, hv.z, a0); a0 = fmaf(wreg[i].w, hv.w, a0);
            if (v1) { float4 w = p1[k];
                a1 = fmaf(w.x, hv.x, a1); a1 = fmaf(w.y, hv.y, a1);
                a1 = fmaf(w.z, hv.z, a1); a1 = fmaf(w.w, hv.w, a1); }
            if (v2) { float4 w = p2[k];
                a2 = fmaf(w.x, hv.x, a2); a2 = fmaf(w.y, hv.y, a2);
                a2 = fmaf(w.z, hv.z, a2); a2 = fmaf(w.w, hv.w, a2); }
        }
#pragma unroll
        for (int off = 16; off; off >>= 1) {
            a0 += __shfl_xor_sync(0xffffffffu, a0, off);
            a1 += __shfl_xor_sync(0xffffffffu, a1, off);
            a2 += __shfl_xor_sync(0xffffffffu, a2, off);
        }
        if (lane == 0) {
            if (v0) sdots[rr0] = a0;
            if (v1) sdots[rr1] = a1;
            if (v2) sdots[rr2] = a2;
        }
        __syncthreads();

        // ---- pointwise GRU update ----
        if (doPoint) {
            float hr = sdots[tid];
            float hz = sdots[nj + tid];
            float hn = sdots[2 * nj + tid];
            float r  = 1.f / (1.f + expf(-(gr + hr)));
            float u  = 1.f / (1.f + expf(-(gz + hz)));
            float nv = tanhf(gnv + r * (hn + mybn));
            float hprev = sh[myj];
            float hnext = (1.f - u) * nv + u * hprev;
            out[(size_t)t * H + myj] = hnext;
            if (t == T - 1) out[(size_t)T * H + myj] = hnext;  // last_state
        }

        // ---- grid barrier (arrive, prefetch next igates, then wait) ----
        __threadfence();
        __syncthreads();
        if (tid == 0) {
            unsigned a = atomicAdd(&g_bar_count, 1u);
            if (a == (unsigned)NB - 1u) {
                g_bar_count = 0u;
                __threadfence();
                atomicAdd(&g_bar_gen, 1u);
            }
        }
        // overlap: issue next step's igate loads while barrier resolves
        if (doPoint && (t + 1) < T) {
            const float* igt = g_ig + (size_t)(t + 1) * G3;
            gr  = igt[myj];
            gz  = igt[H + myj];
            gnv = igt[2 * H + myj];
        }
        if (tid == 0) {
            while (*reinterpret_cast<volatile unsigned*>(&g_bar_gen) == seen) {
                __nanosleep(32);
            }
            __threadfence();
        }
        __syncthreads();
        seen++;
    }
}

// =================================================================
// launch
// =================================================================
extern "C" void kernel_launch(void* const* d_in, const int* in_sizes, int n_in,
                              void* d_out, int out_size)
{
    const float* xs         = (const float*)d_in[0];  // [4096,2048]
    const float* init_state = (const float*)d_in[1];  // [2048]
    const float* Wi         = (const float*)d_in[2];  // [6144,2048]
    const float* Wh         = (const float*)d_in[3];  // [6144,2048]
    const float* bi         = (const float*)d_in[4];  // [6144]
    const float* bn         = (const float*)d_in[5];  // [2048]
    float* out              = (float*)d_out;          // [4096*2048 + 2048]

    (void)in_sizes; (void)n_in; (void)out_size;

    // 1) input-gate GEMM: grid (N/BN, M/BM) = (48, 32)
    igates_gemm<<<dim3(G3 / BN, T / BM), 256>>>(xs, Wi, bi);

    // 2) persistent scan: one CTA per SM
    int dev = 0;
    cudaGetDevice(&dev);
    int nsm = 148;
    cudaDeviceGetAttribute(&nsm, cudaDevAttrMultiProcessorCount, dev);
    if (nsm < 1) nsm = 148;

    cudaFuncSetAttribute(gru_scan, cudaFuncAttributeMaxDynamicSharedMemorySize, SCAN_SMEM);
    gru_scan<<<nsm, 512, SCAN_SMEM>>>(Wh, init_state, bn, out);
}

// round 6
// speedup vs baseline: 1.1703x; 1.1703x over previous
#include <cuda_runtime.h>
#include <math.h>

#define H     2048
#define T     4096
#define G3    (3 * H)
#define K_IN  2048
#define NBMAX 160

// ---------------- device scratch / barrier state ----------------
__device__ float    g_ig[(size_t)T * G3];      // igates [T][3H]
__device__ unsigned g_flags[NBMAX * 8];        // per-CTA epoch flags, 32B stride

// =================================================================
// Kernel 1: igates = xs @ Wi^T + bi    (fp32 SMEM-tiled GEMM)
// =================================================================
#define BM 128
#define BN 128
#define BK 16

__global__ __launch_bounds__(256, 2)
void igates_gemm(const float* __restrict__ A,
                 const float* __restrict__ B,
                 const float* __restrict__ bi)
{
    __shared__ float As[BK][BM + 4];
    __shared__ float Bs[BK][BN + 4];

    const int tid = threadIdx.x;
    const int m0  = blockIdx.y * BM;
    const int n0  = blockIdx.x * BN;
    const int tx  = tid & 15;
    const int ty  = tid >> 4;

    float acc[8][8];
#pragma unroll
    for (int i = 0; i < 8; i++)
#pragma unroll
        for (int j = 0; j < 8; j++) acc[i][j] = 0.f;

    for (int k0 = 0; k0 < K_IN; k0 += BK) {
#pragma unroll
        for (int p = 0; p < 2; p++) {
            int f   = tid + p * 256;
            int row = f >> 2;
            int c4  = (f & 3) * 4;
            float4 va = *reinterpret_cast<const float4*>(
                &A[(size_t)(m0 + row) * K_IN + k0 + c4]);
            As[c4 + 0][row] = va.x; As[c4 + 1][row] = va.y;
            As[c4 + 2][row] = va.z; As[c4 + 3][row] = va.w;
            float4 vb = *reinterpret_cast<const float4*>(
                &B[(size_t)(n0 + row) * K_IN + k0 + c4]);
            Bs[c4 + 0][row] = vb.x; Bs[c4 + 1][row] = vb.y;
            Bs[c4 + 2][row] = vb.z; Bs[c4 + 3][row] = vb.w;
        }
        __syncthreads();

#pragma unroll
        for (int kk = 0; kk < BK; kk++) {
            float a[8], b[8];
            *reinterpret_cast<float4*>(&a[0]) = *reinterpret_cast<float4*>(&As[kk][ty * 8]);
            *reinterpret_cast<float4*>(&a[4]) = *reinterpret_cast<float4*>(&As[kk][ty * 8 + 4]);
            *reinterpret_cast<float4*>(&b[0]) = *reinterpret_cast<float4*>(&Bs[kk][tx * 8]);
            *reinterpret_cast<float4*>(&b[4]) = *reinterpret_cast<float4*>(&Bs[kk][tx * 8 + 4]);
#pragma unroll
            for (int i = 0; i < 8; i++)
#pragma unroll
                for (int j = 0; j < 8; j++)
                    acc[i][j] = fmaf(a[i], b[j], acc[i][j]);
        }
        __syncthreads();
    }

#pragma unroll
    for (int i = 0; i < 8; i++) {
        int m = m0 + ty * 8 + i;
#pragma unroll
        for (int j = 0; j < 8; j += 4) {
            int n = n0 + tx * 8 + j;
            float4 v;
            v.x = acc[i][j + 0] + bi[n + 0];
            v.y = acc[i][j + 1] + bi[n + 1];
            v.z = acc[i][j + 2] + bi[n + 2];
            v.w = acc[i][j + 3] + bi[n + 3];
            *reinterpret_cast<float4*>(&g_ig[(size_t)m * G3 + n]) = v;
        }
    }
}

// ---------------- release / acquire helpers ----------------
__device__ __forceinline__ void flag_release(unsigned* p, unsigned v) {
    asm volatile("st.release.gpu.global.u32 [%0], %1;" :: "l"(p), "r"(v) : "memory");
}
__device__ __forceinline__ unsigned flag_acquire(const unsigned* p) {
    unsigned v;
    asm volatile("ld.acquire.gpu.global.u32 %0, [%1];" : "=r"(v) : "l"(p) : "memory");
    return v;
}

// =================================================================
// Kernel 2: persistent GRU scan, fully weight-resident (regs+SMEM)
//   148 CTAs x 256 threads (8 warps), 1 CTA/SM.
//   Row slot rr = s*8 + warp, s=0..5.
//     slots 0,1 (16 rows): weights in REGISTERS
//     slots 2..5 (<=26 rows): weights in SMEM (loaded once)
//   Grid sync: per-CTA epoch flags (st.release / ld.acquire), no atomics.
// =================================================================
#define NSR_MAX 26
#define SCAN_SMEM ((NSR_MAX * H + H + 64) * 4)   // 221,440 bytes

__global__ __launch_bounds__(256, 1)
void gru_scan(const float* __restrict__ Wh,
              const float* __restrict__ init_state,
              const float* __restrict__ bn,
              float* __restrict__ out)
{
    extern __shared__ float smem[];
    const int NB   = gridDim.x;
    const int cta  = blockIdx.x;
    const int tid  = threadIdx.x;
    const int lane = tid & 31;
    const int warp = tid >> 5;          // 0..7

    const int chunk = (H + NB - 1) / NB;
    const int j0    = cta * chunk;
    int nj = H - j0;
    if (nj > chunk) nj = chunk;
    if (nj < 0) nj = 0;
    const int nrows = 3 * nj;

    float* sw    = smem;                 // NSR_MAX rows x 2048 (rows 16..41)
    float* sh    = smem + NSR_MAX * H;   // staged h (2048)
    float* sdots = sh + H;               // 48 dot results
    float4* sh4  = reinterpret_cast<float4*>(sh);

    // epoch base: own flag from previous completed launch (all flags equal)
    const unsigned epoch = g_flags[cta * 8];

    // ---- preload SMEM-resident weight rows (rr = 16..nrows-1), once ----
    const int nsr = (nrows > 16) ? (nrows - 16) : 0;   // <= 26
    for (int idx = tid; idx < nsr * (H / 4); idx += 256) {
        int r  = idx >> 9;
        int c  = idx & 511;
        int rr = 16 + r;
        int g  = rr / nj;
        int jj = rr - g * nj;
        reinterpret_cast<float4*>(sw)[r * (H / 4) + c] =
            reinterpret_cast<const float4*>(Wh + (size_t)(g * H + j0 + jj) * H)[c];
    }

    // ---- per-warp row slots ----
    const int rr0 = warp,      rr1 = warp + 8,  rr2 = warp + 16;
    const int rr3 = warp + 24, rr4 = warp + 32, rr5 = warp + 40;
    const bool v0 = rr0 < nrows, v1 = rr1 < nrows, v2 = rr2 < nrows;
    const bool v3 = rr3 < nrows, v4 = rr4 < nrows, v5 = rr5 < nrows;

    // ---- register-resident weights for slots 0,1 ----
    float4 wreg0[16], wreg1[16];
    {
        const float* row;
        int g, jj;
        g = v0 ? (rr0 / nj) : 0; jj = v0 ? (rr0 - g * nj) : 0;
        row = Wh + (size_t)(g * H + j0 + jj) * H;
#pragma unroll
        for (int i = 0; i < 16; i++)
            wreg0[i] = reinterpret_cast<const float4*>(row)[lane + 32 * i];
        g = v1 ? (rr1 / nj) : 0; jj = v1 ? (rr1 - g * nj) : 0;
        row = Wh + (size_t)(g * H + j0 + jj) * H;
#pragma unroll
        for (int i = 0; i < 16; i++)
            wreg1[i] = reinterpret_cast<const float4*>(row)[lane + 32 * i];
    }

    const float4* p2 = reinterpret_cast<const float4*>(v2 ? (sw + (rr2 - 16) * H) : sw);
    const float4* p3 = reinterpret_cast<const float4*>(v3 ? (sw + (rr3 - 16) * H) : sw);
    const float4* p4 = reinterpret_cast<const float4*>(v4 ? (sw + (rr4 - 16) * H) : sw);
    const float4* p5 = reinterpret_cast<const float4*>(v5 ? (sw + (rr5 - 16) * H) : sw);

    const bool doPoint = (tid < nj);
    const int  myj     = j0 + (doPoint ? tid : 0);
    const float mybn   = doPoint ? bn[myj] : 0.f;

    // prefetch igates for t = 0
    float gr = 0.f, gz = 0.f, gnv = 0.f;
    if (doPoint) {
        gr  = g_ig[myj];
        gz  = g_ig[H + myj];
        gnv = g_ig[2 * H + myj];
    }

    __syncthreads();   // SMEM weights ready

#pragma unroll 1
    for (int t = 0; t < T; t++) {
        // ---- stage h_{t-1} into SMEM (8 KB from L2) ----
        const float* hsrc = (t == 0) ? init_state : (out + (size_t)(t - 1) * H);
#pragma unroll
        for (int p = 0; p < 2; p++)
            sh4[tid + p * 256] = reinterpret_cast<const float4*>(hsrc)[tid + p * 256];
        __syncthreads();

        // ---- six dot products per warp ----
        float a0 = 0.f, a1 = 0.f, a2 = 0.f, a3 = 0.f, a4 = 0.f, a5 = 0.f;
#pragma unroll
        for (int i = 0; i < 16; i++) {
            const int k = lane + 32 * i;
            const float4 hv = sh4[k];
            a0 = fmaf(wreg0[i].x, hv.x, a0); a0 = fmaf(wreg0[i].y, hv.y, a0);
            a0 = fmaf(wreg0[i].z, hv.z, a0); a0 = fmaf(wreg0[i].w, hv.w, a0);
            a1 = fmaf(wreg1[i].x, hv.x, a1); a1 = fmaf(wreg1[i].y, hv.y, a1);
            a1 = fmaf(wreg1[i].z, hv.z, a1); a1 = fmaf(wreg1[i].w, hv.w, a1);
            if (v2) { float4 w = p2[k];
                a2 = fmaf(w.x, hv.x, a2); a2 = fmaf(w.y, hv.y, a2);
                a2 = fmaf(w.z, hv.z, a2); a2 = fmaf(w.w, hv.w, a2); }
            if (v3) { float4 w = p3[k];
                a3 = fmaf(w.x, hv.x, a3); a3 = fmaf(w.y, hv.y, a3);
                a3 = fmaf(w.z, hv.z, a3); a3 = fmaf(w.w, hv.w, a3); }
            if (v4) { float4 w = p4[k];
                a4 = fmaf(w.x, hv.x, a4); a4 = fmaf(w.y, hv.y, a4);
                a4 = fmaf(w.z, hv.z, a4); a4 = fmaf(w.w, hv.w, a4); }
            if (v5) { float4 w = p5[k];
                a5 = fmaf(w.x, hv.x, a5); a5 = fmaf(w.y, hv.y, a5);
                a5 = fmaf(w.z, hv.z, a5); a5 = fmaf(w.w, hv.w, a5); }
        }
#pragma unroll
        for (int off = 16; off; off >>= 1) {
            a0 += __shfl_xor_sync(0xffffffffu, a0, off);
            a1 += __shfl_xor_sync(0xffffffffu, a1, off);
            a2 += __shfl_xor_sync(0xffffffffu, a2, off);
            a3 += __shfl_xor_sync(0xffffffffu, a3, off);
            a4 += __shfl_xor_sync(0xffffffffu, a4, off);
            a5 += __shfl_xor_sync(0xffffffffu, a5, off);
        }
        if (lane == 0) {
            if (v0) sdots[rr0] = a0;
            if (v1) sdots[rr1] = a1;
            if (v2) sdots[rr2] = a2;
            if (v3) sdots[rr3] = a3;
            if (v4) sdots[rr4] = a4;
            if (v5) sdots[rr5] = a5;
        }
        __syncthreads();

        // ---- pointwise GRU update (fast transcendentals) ----
        if (doPoint) {
            float hr = sdots[tid];
            float hz = sdots[nj + tid];
            float hn = sdots[2 * nj + tid];
            float r  = __fdividef(1.f, 1.f + __expf(-(gr + hr)));
            float u  = __fdividef(1.f, 1.f + __expf(-(gz + hz)));
            float x  = gnv + r * (hn + mybn);
            float nv = __fdividef(2.f, 1.f + __expf(-2.f * x)) - 1.f;  // tanh
            float hprev = sh[myj];
            float hnext = (1.f - u) * nv + u * hprev;
            out[(size_t)t * H + myj] = hnext;
            if (t == T - 1) out[(size_t)T * H + myj] = hnext;  // last_state
        }

        // ---- grid barrier: post own flag, prefetch, wait for all ----
        const unsigned target = epoch + (unsigned)(t + 1);
        __syncthreads();                       // all h stores issued
        if (tid == 0)
            flag_release(&g_flags[cta * 8], target);

        // overlap: issue next step's igate loads while barrier resolves
        if (doPoint && (t + 1) < T) {
            const float* igt = g_ig + (size_t)(t + 1) * G3;
            gr  = igt[myj];
            gz  = igt[H + myj];
            gnv = igt[2 * H + myj];
        }

        // parallel flag check: 148 threads, one flag each
        for (;;) {
            bool p = true;
            if (tid < NB)
                p = ((int)(flag_acquire(&g_flags[tid * 8]) - target) >= 0);
            if (__syncthreads_and(p)) break;
        }
    }
}

// =================================================================
// launch
// =================================================================
extern "C" void kernel_launch(void* const* d_in, const int* in_sizes, int n_in,
                              void* d_out, int out_size)
{
    const float* xs         = (const float*)d_in[0];  // [4096,2048]
    const float* init_state = (const float*)d_in[1];  // [2048]
    const float* Wi         = (const float*)d_in[2];  // [6144,2048]
    const float* Wh         = (const float*)d_in[3];  // [6144,2048]
    const float* bi         = (const float*)d_in[4];  // [6144]
    const float* bn         = (const float*)d_in[5];  // [2048]
    float* out              = (float*)d_out;          // [4096*2048 + 2048]

    (void)in_sizes; (void)n_in; (void)out_size;

    // 1) input-gate GEMM: grid (N/BN, M/BM) = (48, 32)
    igates_gemm<<<dim3(G3 / BN, T / BM), 256>>>(xs, Wi, bi);

    // 2) persistent scan: one CTA per SM
    int dev = 0;
    cudaGetDevice(&dev);
    int nsm = 148;
    cudaDeviceGetAttribute(&nsm, cudaDevAttrMultiProcessorCount, dev);
    if (nsm < 1) nsm = 148;
    if (nsm > NBMAX) nsm = NBMAX;

    cudaFuncSetAttribute(gru_scan, cudaFuncAttributeMaxDynamicSharedMemorySize, SCAN_SMEM);
    gru_scan<<<nsm, 256, SCAN_SMEM>>>(Wh, init_state, bn, out);
}